// round 15
// baseline (speedup 1.0000x reference)
#include <cuda_runtime.h>
#include <cuda_bf16.h>
#include <cstddef>
#include <cstdint>

// ---------------- problem constants ----------------
#define HID   4096
#define DSZ   256
#define MSLOT 64
#define BATCH 4
#define NTOK  4096
#define BNTOK (BATCH * NTOK)
#define LCOLS 128
#define NXC   4

typedef unsigned long long u64;

// ---------------- packed fp32x2 helpers ----------------
__device__ __forceinline__ u64 pack2(float x, float y) {
    u64 r; asm("mov.b64 %0, {%1, %2};" : "=l"(r) : "f"(x), "f"(y)); return r;
}
__device__ __forceinline__ void unpack2(u64 v, float& x, float& y) {
    asm("mov.b64 {%0, %1}, %2;" : "=f"(x), "=f"(y) : "l"(v));
}
__device__ __forceinline__ void ffma2(u64& d, u64 a, u64 b) {
    asm("fma.rn.f32x2 %0, %1, %2, %0;" : "+l"(d) : "l"(a), "l"(b));
}
__device__ __forceinline__ uint32_t smem_u32(const void* p) {
    uint32_t a;
    asm("{ .reg .u64 t; cvta.to.shared.u64 t, %1; cvt.u32.u64 %0, t; }" : "=r"(a) : "l"(p));
    return a;
}

// ---------------- cp.async helpers ----------------
__device__ __forceinline__ void cp_async16(uint32_t dst, const void* src) {
    asm volatile("cp.async.cg.shared.global [%0], [%1], 16;" :: "r"(dst), "l"(src));
}
#define CP_COMMIT() asm volatile("cp.async.commit_group;" ::: "memory")
#define CP_WAIT0()  asm volatile("cp.async.wait_group 0;" ::: "memory")

// ---------------- mma.sync helpers ----------------
__device__ __forceinline__ void ldsm_x4(uint32_t& a0, uint32_t& a1, uint32_t& a2, uint32_t& a3,
                                        uint32_t addr) {
    asm volatile("ldmatrix.sync.aligned.m8n8.x4.shared.b16 {%0,%1,%2,%3}, [%4];"
                 : "=r"(a0), "=r"(a1), "=r"(a2), "=r"(a3) : "r"(addr));
}
__device__ __forceinline__ void ldsm_x4_t(uint32_t& a0, uint32_t& a1, uint32_t& a2, uint32_t& a3,
                                          uint32_t addr) {
    asm volatile("ldmatrix.sync.aligned.m8n8.x4.trans.shared.b16 {%0,%1,%2,%3}, [%4];"
                 : "=r"(a0), "=r"(a1), "=r"(a2), "=r"(a3) : "r"(addr));
}
__device__ __forceinline__ void mma_bf16(float* d, const uint32_t* a, const uint32_t* b) {
    asm volatile("mma.sync.aligned.m16n8k16.row.col.f32.bf16.bf16.f32 "
                 "{%0,%1,%2,%3}, {%4,%5,%6,%7}, {%8,%9}, {%0,%1,%2,%3};"
                 : "+f"(d[0]), "+f"(d[1]), "+f"(d[2]), "+f"(d[3])
                 : "r"(a[0]), "r"(a[1]), "r"(a[2]), "r"(a[3]), "r"(b[0]), "r"(b[1]));
}

__device__ __forceinline__ void split4(unsigned short* Hi, unsigned short* Lo,
                                       size_t off, float4 v) {
    __nv_bfloat16 h0 = __float2bfloat16_rn(v.x), h1 = __float2bfloat16_rn(v.y);
    __nv_bfloat16 h2 = __float2bfloat16_rn(v.z), h3 = __float2bfloat16_rn(v.w);
    __nv_bfloat16 l0 = __float2bfloat16_rn(v.x - __bfloat162float(h0));
    __nv_bfloat16 l1 = __float2bfloat16_rn(v.y - __bfloat162float(h1));
    __nv_bfloat16 l2 = __float2bfloat16_rn(v.z - __bfloat162float(h2));
    __nv_bfloat16 l3 = __float2bfloat16_rn(v.w - __bfloat162float(h3));
    *reinterpret_cast<ushort4*>(&Hi[off]) =
        make_ushort4(__bfloat16_as_ushort(h0), __bfloat16_as_ushort(h1),
                     __bfloat16_as_ushort(h2), __bfloat16_as_ushort(h3));
    *reinterpret_cast<ushort4*>(&Lo[off]) =
        make_ushort4(__bfloat16_as_ushort(l0), __bfloat16_as_ushort(l1),
                     __bfloat16_as_ushort(l2), __bfloat16_as_ushort(l3));
}

// ---------------- scratch ----------------
__device__ __nv_bfloat16 g_wh[LCOLS * HID];
__device__ __nv_bfloat16 g_wl[LCOLS * HID];
__device__ float g_qsb[MSLOT];
__device__ __nv_bfloat16 g_swh[(size_t)BNTOK * MSLOT];
__device__ __nv_bfloat16 g_swl[(size_t)BNTOK * MSLOT];
__device__ float g_S[BATCH * MSLOT];
__device__ float g_Xp[NXC][BATCH * MSLOT * HID];
__device__ float g_svp[8][BATCH * MSLOT * DSZ];
__device__ float g_so[BATCH * MSLOT * HID];

// ---------------- K1: merged prep: qs_w rows / gate_w split / qsb / zero g_S ----
__global__ __launch_bounds__(128) void k_prep(const float* __restrict__ slots,
                                              const float* __restrict__ q_w,
                                              const float* __restrict__ q_b,
                                              const float* __restrict__ gw) {
    const int y = blockIdx.y;
    if (y < 4) {
        __shared__ float s_slot[16 * DSZ];
        const int mg = y * 16;
        const int h  = blockIdx.x * 128 + threadIdx.x;
#pragma unroll
        for (int j = 0; j < 8; j++) {
            const int idx = threadIdx.x + j * 128;
            const int mm = idx >> 6, dq = (idx & 63) << 2;
            *reinterpret_cast<float4*>(&s_slot[mm * DSZ + dq]) =
                *reinterpret_cast<const float4*>(&slots[(size_t)(mg + mm) * DSZ + dq]);
        }
        __syncthreads();
        float acc[16];
#pragma unroll
        for (int i = 0; i < 16; i++) acc[i] = 0.f;
        for (int d = 0; d < DSZ; d++) {
            const float w = q_w[(size_t)d * HID + h];
#pragma unroll
            for (int i = 0; i < 16; i++) acc[i] += s_slot[i * DSZ + d] * w;
        }
#pragma unroll
        for (int i = 0; i < 16; i++) {
            const __nv_bfloat16 hi = __float2bfloat16_rn(acc[i]);
            const __nv_bfloat16 lo = __float2bfloat16_rn(acc[i] - __bfloat162float(hi));
            g_wh[(size_t)(64 + mg + i) * HID + h] = hi;
            g_wl[(size_t)(64 + mg + i) * HID + h] = lo;
        }
        if (blockIdx.x == 0 && y == 0) {
            g_S[threadIdx.x] = 0.f;
            g_S[threadIdx.x + 128] = 0.f;
            if (threadIdx.x < MSLOT) {
                float b = 0.f;
                for (int d = 0; d < DSZ; d++)
                    b += slots[(size_t)threadIdx.x * DSZ + d] * q_b[d];
                g_qsb[threadIdx.x] = b;
            }
        }
    } else {
        // gate_w -> g_wh/g_wl[0..63]; 65536 float4 over 64 blocks * 128 thr * 8
        const int gidx = (blockIdx.x * 2 + (y - 4)) * 128 + threadIdx.x;   // 0..8191
#pragma unroll
        for (int j = 0; j < 8; j++) {
            const int f4 = j * 8192 + gidx;
            const int r = f4 >> 10, q = (f4 & 1023) << 2;
            const float4 v = *reinterpret_cast<const float4*>(&gw[(size_t)r * HID + q]);
            split4(reinterpret_cast<unsigned short*>(g_wh),
                   reinterpret_cast<unsigned short*>(g_wl), (size_t)r * HID + q, v);
        }
    }
}

// ---------------- K2: fused logits GEMM + dual softmax (M128, hoisted offsets) ----
#define KC  32
#define SH  40
#define NCH (HID / KC)            // 128
#define LTA (128 * SH)            // 5120 halfs per tile
#define LST (4 * LTA)             // stage = 20480 halfs
#define LG_SMEM (2 * LST * 2)     // 81920 bytes

__global__ __launch_bounds__(512) void k_logits_f(const float* __restrict__ hs,
                                                  const float* __restrict__ gb,
                                                  float* __restrict__ gates_out) {
    extern __shared__ __align__(16) unsigned short ls[];
    const int tid = threadIdx.x;
    const int wid = tid >> 5, lane = tid & 31;
    const int row0 = blockIdx.x * 128;
    const int wm = wid >> 2, wn = wid & 3;
    const uint32_t base_u = smem_u32(ls);

    // hoisted LDSM offsets (halfs*2 = bytes), indexed [kk/16][np or mi]
    uint32_t lboff[2][2], laoff[2][2];
    {
        const int nrow = (lane >> 4) * 8 + (lane & 7);
#pragma unroll
        for (int j = 0; j < 2; j++) {
            const int bcol = j * 16 + ((lane >> 3) & 1) * 8;
#pragma unroll
            for (int np = 0; np < 2; np++)
                lboff[j][np] = (uint32_t)((wn * 32 + np * 16 + nrow) * SH + bcol) * 2;
            const int acol = j * 16 + (lane >> 4) * 8;
#pragma unroll
            for (int mi = 0; mi < 2; mi++)
                laoff[j][mi] = (uint32_t)((wm * 32 + mi * 16 + (lane & 15)) * SH + acol) * 2;
        }
    }

    float acc[2][4][4];
#pragma unroll
    for (int i = 0; i < 2; i++)
#pragma unroll
        for (int j = 0; j < 4; j++)
#pragma unroll
            for (int f = 0; f < 4; f++) acc[i][j][f] = 0.f;

    float4 ar[2];
#pragma unroll
    for (int t = 0; t < 2; t++) {
        const int idx = tid + t * 512;
        const int hf = idx >> 9, rem = idx & 511;
        const int r = rem >> 2, q = rem & 3;
        const __nv_bfloat16* src = (hf ? g_wl : g_wh) + (size_t)r * HID + q * 8;
        cp_async16(base_u + (uint32_t)((2 + hf) * LTA + r * SH + q * 8) * 2, src);
    }
    CP_COMMIT();
#pragma unroll
    for (int t = 0; t < 2; t++) {
        const int idx = tid + t * 512, r = idx >> 3, q = idx & 7;
        ar[t] = *reinterpret_cast<const float4*>(&hs[(size_t)(row0 + r) * HID + q * 4]);
    }
#pragma unroll
    for (int t = 0; t < 2; t++) {
        const int idx = tid + t * 512, r = idx >> 3, q = idx & 7;
        split4(ls, ls + LTA, r * SH + q * 4, ar[t]);
    }
#pragma unroll
    for (int t = 0; t < 2; t++) {
        const int idx = tid + t * 512, r = idx >> 3, q = idx & 7;
        ar[t] = *reinterpret_cast<const float4*>(&hs[(size_t)(row0 + r) * HID + KC + q * 4]);
    }

    auto kstep = [&](uint32_t ah_u, uint32_t al_u, uint32_t bh_u, uint32_t bl_u, int j) {
        uint32_t bhf[4][2], blf[4][2];
#pragma unroll
        for (int np = 0; np < 2; np++) {
            ldsm_x4(bhf[2 * np][0], bhf[2 * np][1], bhf[2 * np + 1][0], bhf[2 * np + 1][1],
                    bh_u + lboff[j][np]);
            ldsm_x4(blf[2 * np][0], blf[2 * np][1], blf[2 * np + 1][0], blf[2 * np + 1][1],
                    bl_u + lboff[j][np]);
        }
#pragma unroll
        for (int mi = 0; mi < 2; mi++) {
            uint32_t ahf[4], alf[4];
            ldsm_x4(ahf[0], ahf[1], ahf[2], ahf[3], ah_u + laoff[j][mi]);
            ldsm_x4(alf[0], alf[1], alf[2], alf[3], al_u + laoff[j][mi]);
#pragma unroll
            for (int ni = 0; ni < 4; ni++) {
                mma_bf16(acc[mi][ni], ahf, bhf[ni]);
                mma_bf16(acc[mi][ni], ahf, blf[ni]);
                mma_bf16(acc[mi][ni], alf, bhf[ni]);
            }
        }
    };

    for (int c = 0; c < NCH; c++) {
        const int s = c & 1;
        CP_WAIT0();
        __syncthreads();
        if (c + 1 < NCH) {
            const int k0 = (c + 1) * KC;
            const uint32_t st1 = (uint32_t)((s ^ 1) * LST);
#pragma unroll
            for (int t = 0; t < 2; t++) {
                const int idx = tid + t * 512;
                const int hf = idx >> 9, rem = idx & 511;
                const int r = rem >> 2, q = rem & 3;
                const __nv_bfloat16* src = (hf ? g_wl : g_wh) + (size_t)r * HID + k0 + q * 8;
                cp_async16(base_u + (st1 + (2 + hf) * LTA + r * SH + q * 8) * 2, src);
            }
            CP_COMMIT();
        }
        const uint32_t ah_u = base_u + (uint32_t)(s * LST) * 2;
        const uint32_t al_u = ah_u + LTA * 2;
        const uint32_t bh_u = ah_u + 2 * LTA * 2;
        const uint32_t bl_u = ah_u + 3 * LTA * 2;

        kstep(ah_u, al_u, bh_u, bl_u, 0);
        if (c + 1 < NCH) {
            unsigned short* Ah1 = ls + (s ^ 1) * LST;
#pragma unroll
            for (int t = 0; t < 2; t++) {
                const int idx = tid + t * 512, r = idx >> 3, q = idx & 7;
                split4(Ah1, Ah1 + LTA, r * SH + q * 4, ar[t]);
            }
            if (c + 2 < NCH) {
                const int k2 = (c + 2) * KC;
#pragma unroll
                for (int t = 0; t < 2; t++) {
                    const int idx = tid + t * 512, r = idx >> 3, q = idx & 7;
                    ar[t] = *reinterpret_cast<const float4*>(
                        &hs[(size_t)(row0 + r) * HID + k2 + q * 4]);
                }
            }
        }
        kstep(ah_u, al_u, bh_u, bl_u, 1);
    }

    __syncthreads();
    float* sl = reinterpret_cast<float*>(ls);
    const int qr = lane >> 2, qc = (lane & 3) * 2;
#pragma unroll
    for (int mi = 0; mi < 2; mi++) {
        const int lr = wm * 32 + mi * 16 + qr;
#pragma unroll
        for (int ni = 0; ni < 4; ni++) {
            const int c0 = wn * 32 + ni * 8 + qc;
            const float b0 = (c0 < 64) ? gb[c0] : g_qsb[c0 - 64];
            const float b1 = (c0 + 1 < 64) ? gb[c0 + 1] : g_qsb[c0 + 1 - 64];
            sl[lr * 132 + c0]           = acc[mi][ni][0] + b0;
            sl[lr * 132 + c0 + 1]       = acc[mi][ni][1] + b1;
            sl[(lr + 8) * 132 + c0]     = acc[mi][ni][2] + b0;
            sl[(lr + 8) * 132 + c0 + 1] = acc[mi][ni][3] + b1;
        }
    }
    __syncthreads();

    const int b = row0 >> 12;
    float s0 = 0.f, s1 = 0.f;
#pragma unroll
    for (int rr = 0; rr < 8; rr++) {
        const int row = wid * 8 + rr;
        const size_t n = row0 + row;
        const float* rp = sl + row * 132;
        {
            float g0 = rp[lane], g1 = rp[32 + lane];
            float mx = fmaxf(g0, g1);
#pragma unroll
            for (int o = 16; o; o >>= 1) mx = fmaxf(mx, __shfl_xor_sync(0xffffffffu, mx, o));
            float e0 = __expf(g0 - mx), e1 = __expf(g1 - mx);
            float ss = e0 + e1;
#pragma unroll
            for (int o = 16; o; o >>= 1) ss += __shfl_xor_sync(0xffffffffu, ss, o);
            const float inv = 1.f / ss;
            gates_out[n * MSLOT + lane]      = e0 * inv;
            gates_out[n * MSLOT + 32 + lane] = e1 * inv;
        }
        {
            float g0 = rp[64 + lane], g1 = rp[96 + lane];
            float mx = fmaxf(g0, g1);
#pragma unroll
            for (int o = 16; o; o >>= 1) mx = fmaxf(mx, __shfl_xor_sync(0xffffffffu, mx, o));
            float e0 = __expf(g0 - mx), e1 = __expf(g1 - mx);
            float ss = e0 + e1;
#pragma unroll
            for (int o = 16; o; o >>= 1) ss += __shfl_xor_sync(0xffffffffu, ss, o);
            const float inv = 1.f / ss;
            const float w0 = e0 * inv, w1 = e1 * inv;
            const __nv_bfloat16 h0 = __float2bfloat16_rn(w0);
            const __nv_bfloat16 h1 = __float2bfloat16_rn(w1);
            g_swh[n * MSLOT + lane]      = h0;
            g_swh[n * MSLOT + 32 + lane] = h1;
            g_swl[n * MSLOT + lane]      = __float2bfloat16_rn(w0 - __bfloat162float(h0));
            g_swl[n * MSLOT + 32 + lane] = __float2bfloat16_rn(w1 - __bfloat162float(h1));
            s0 += w0; s1 += w1;
        }
    }
    atomicAdd(&g_S[b * MSLOT + lane], s0);
    atomicAdd(&g_S[b * MSLOT + 32 + lane], s1);
}

// ---------------- K4: X partials — hoisted offsets, 3 CTAs/SM ----------------
#define XSA 72
#define XSB 136
#define TB  32
#define XT_A (TB * XSA)
#define XT_B (TB * XSB)
#define X_STAGE (2 * XT_A + 2 * XT_B)            // 13312 halfs
#define XSM_BYTES (2 * X_STAGE * 2)              // 53248 bytes
#define XITS (1024 / TB)                         // 32

__global__ __launch_bounds__(256, 3) void k_X_h(const float* __restrict__ hs) {
    extern __shared__ __align__(16) unsigned short xs[];
    const int tid = threadIdx.x, wid = tid >> 5, lane = tid & 31;
    const int h0 = blockIdx.x * 128, b = blockIdx.y, nc = blockIdx.z;
    const int wm = wid >> 2, wn = wid & 3;
    const uint32_t base_u = smem_u32(xs);
    const int A_OFF = 0, AL_OFF = XT_A, BH_OFF = 2 * XT_A, BL_OFF = 2 * XT_A + XT_B;
    const int nbase = nc * 1024;

    // hoisted LDSM offsets (bytes), indexed [kk/16][np or mi]
    uint32_t xboff[2][2], xaoff[2][2];
    {
#pragma unroll
        for (int j = 0; j < 2; j++) {
            const int krow = j * 16 + ((lane >> 3) & 1) * 8 + (lane & 7);
            const int cadd = (lane >> 4) * 8;
#pragma unroll
            for (int np = 0; np < 2; np++)
                xboff[j][np] = (uint32_t)(krow * XSB + wn * 32 + np * 16 + cadd) * 2;
            const int arow = j * 16 + ((lane >> 4) & 1) * 8 + (lane & 7);
            const int acsel = ((lane >> 3) & 1) * 8;
#pragma unroll
            for (int mi = 0; mi < 2; mi++)
                xaoff[j][mi] = (uint32_t)(arow * XSA + wm * 32 + mi * 16 + acsel) * 2;
        }
    }

    float acc[2][4][4];
#pragma unroll
    for (int i = 0; i < 2; i++)
#pragma unroll
        for (int j = 0; j < 4; j++)
#pragma unroll
            for (int f = 0; f < 4; f++) acc[i][j][f] = 0.f;

    float4 br[4];
#pragma unroll
    for (int t = 0; t < 2; t++) {
        const int idx = tid + t * 256;
        const int hf = idx >> 8, rem = idx & 255;
        const int r = rem >> 3, q = rem & 7;
        const __nv_bfloat16* src = (hf ? g_swl : g_swh) +
            ((size_t)(b * NTOK + nbase + r)) * MSLOT + q * 8;
        cp_async16(base_u + (uint32_t)((hf ? AL_OFF : A_OFF) + r * XSA + q * 8) * 2, src);
    }
    CP_COMMIT();
#pragma unroll
    for (int t = 0; t < 4; t++) {
        const int idx = tid + t * 256;
        const int n = idx >> 5, hq = (idx & 31) * 4;
        br[t] = *reinterpret_cast<const float4*>(
            &hs[((size_t)(b * NTOK + nbase + n)) * HID + h0 + hq]);
    }
#pragma unroll
    for (int t = 0; t < 4; t++) {
        const int idx = tid + t * 256;
        const int n = idx >> 5, hq = (idx & 31) * 4;
        split4(xs + BH_OFF, xs + BL_OFF, n * XSB + hq, br[t]);
    }

    auto kstep = [&](uint32_t ah_u, uint32_t al_u, uint32_t bh_u, uint32_t bl_u, int j) {
        uint32_t bhf[4][2], blf[4][2];
#pragma unroll
        for (int np = 0; np < 2; np++) {
            ldsm_x4_t(bhf[2 * np][0], bhf[2 * np][1], bhf[2 * np + 1][0], bhf[2 * np + 1][1],
                      bh_u + xboff[j][np]);
            ldsm_x4_t(blf[2 * np][0], blf[2 * np][1], blf[2 * np + 1][0], blf[2 * np + 1][1],
                      bl_u + xboff[j][np]);
        }
#pragma unroll
        for (int mi = 0; mi < 2; mi++) {
            uint32_t ahf[4], alf[4];
            ldsm_x4_t(ahf[0], ahf[1], ahf[2], ahf[3], ah_u + xaoff[j][mi]);
            ldsm_x4_t(alf[0], alf[1], alf[2], alf[3], al_u + xaoff[j][mi]);
#pragma unroll
            for (int ni = 0; ni < 4; ni++) {
                mma_bf16(acc[mi][ni], ahf, bhf[ni]);
                mma_bf16(acc[mi][ni], ahf, blf[ni]);
                mma_bf16(acc[mi][ni], alf, bhf[ni]);
            }
        }
    };

    for (int it = 0; it < XITS; it++) {
        const int s = it & 1;
        CP_WAIT0();
        __syncthreads();
        if (it + 1 < XITS) {
            const int n0 = nbase + (it + 1) * TB;
#pragma unroll
            for (int t = 0; t < 4; t++) {
                const int idx = tid + t * 256;
                const int n = idx >> 5, hq = (idx & 31) * 4;
                br[t] = *reinterpret_cast<const float4*>(
                    &hs[((size_t)(b * NTOK + n0 + n)) * HID + h0 + hq]);
            }
            const uint32_t st1 = (uint32_t)((s ^ 1) * X_STAGE);
#pragma unroll
            for (int t = 0; t < 2; t++) {
                const int idx = tid + t * 256;
                const int hf = idx >> 8, rem = idx & 255;
                const int r = rem >> 3, q = rem & 7;
                const __nv_bfloat16* src = (hf ? g_swl : g_swh) +
                    ((size_t)(b * NTOK + n0 + r)) * MSLOT + q * 8;
                cp_async16(base_u + (st1 + (hf ? AL_OFF : A_OFF) + r * XSA + q * 8) * 2, src);
            }
            CP_COMMIT();
        }
        const uint32_t ah_u = base_u + (uint32_t)(s * X_STAGE + A_OFF) * 2;
        const uint32_t al_u = base_u + (uint32_t)(s * X_STAGE + AL_OFF) * 2;
        const uint32_t bh_u = base_u + (uint32_t)(s * X_STAGE + BH_OFF) * 2;
        const uint32_t bl_u = base_u + (uint32_t)(s * X_STAGE + BL_OFF) * 2;

        kstep(ah_u, al_u, bh_u, bl_u, 0);
        kstep(ah_u, al_u, bh_u, bl_u, 1);
        if (it + 1 < XITS) {
            unsigned short* Bh1 = xs + (s ^ 1) * X_STAGE + BH_OFF;
            unsigned short* Bl1 = xs + (s ^ 1) * X_STAGE + BL_OFF;
#pragma unroll
            for (int t = 0; t < 4; t++) {
                const int idx = tid + t * 256;
                const int n = idx >> 5, hq = (idx & 31) * 4;
                split4(Bh1, Bl1, n * XSB + hq, br[t]);
            }
        }
    }

    const int qr = lane >> 2, qc = (lane & 3) * 2;
#pragma unroll
    for (int mi = 0; mi < 2; mi++) {
        const int m = wm * 32 + mi * 16 + qr;
#pragma unroll
        for (int ni = 0; ni < 4; ni++) {
            const int h = h0 + wn * 32 + ni * 8 + qc;
            *reinterpret_cast<float2*>(
                &g_Xp[nc][((size_t)(b * MSLOT + m)) * HID + h]) =
                make_float2(acc[mi][ni][0], acc[mi][ni][1]);
            *reinterpret_cast<float2*>(
                &g_Xp[nc][((size_t)(b * MSLOT + m + 8)) * HID + h]) =
                make_float2(acc[mi][ni][2], acc[mi][ni][3]);
        }
    }
}

// ---------------- K5: sv partials (FFMA2), inline g_Xp reduction ----------------
__global__ __launch_bounds__(256) void k_sv(const float* __restrict__ v_w) {
    __shared__ float Asd[16][136];
    __shared__ float Bs[16][136];
    const int tid = threadIdx.x;
    const int d0 = blockIdx.x * 128;
    const int b = blockIdx.y;
    const int kc = blockIdx.z;
    const int tr = tid >> 4, tc = tid & 15;

    u64 acc[4][4];
#pragma unroll
    for (int i = 0; i < 4; i++)
#pragma unroll
        for (int p = 0; p < 4; p++) acc[i][p] = 0ull;

    const int kend = kc * 512 + 512;
    for (int k0 = kc * 512; k0 < kend; k0 += 16) {
        __syncthreads();
        {
            const int m = tid >> 2, kq = (tid & 3) << 2;
            const size_t off = ((size_t)(b * MSLOT + m)) * HID + k0 + kq;
            float4 va = *reinterpret_cast<const float4*>(&g_Xp[0][off]);
#pragma unroll
            for (int c = 1; c < NXC; c++) {
                const float4 vp = *reinterpret_cast<const float4*>(&g_Xp[c][off]);
                va.x += vp.x; va.y += vp.y; va.z += vp.z; va.w += vp.w;
            }
            *reinterpret_cast<u64*>(&Asd[kq + 0][2 * m]) = pack2(va.x, va.x);
            *reinterpret_cast<u64*>(&Asd[kq + 1][2 * m]) = pack2(va.y, va.y);
            *reinterpret_cast<u64*>(&Asd[kq + 2][2 * m]) = pack2(va.z, va.z);
            *reinterpret_cast<u64*>(&Asd[kq + 3][2 * m]) = pack2(va.w, va.w);
        }
#pragma unroll
        for (int i = 0; i < 2; i++) {
            const int idx = tid + i * 256;
            const int c = idx >> 2, kq = (idx & 3) << 2;
            const float4 vb = *reinterpret_cast<const float4*>(
                &v_w[(size_t)(d0 + c) * HID + k0 + kq]);
            Bs[kq + 0][c] = vb.x; Bs[kq + 1][c] = vb.y;
            Bs[kq + 2][c] = vb.z; Bs[kq + 3][c] = vb.w;
        }
        __syncthreads();
#pragma unroll
        for (int k = 0; k < 16; k++) {
            u64 ap[4], bp[4];
#pragma unroll
            for (int i = 0; i < 4; i++)
                ap[i] = *reinterpret_cast<const u64*>(&Asd[k][2 * (tr + 16 * i)]);
#pragma unroll
            for (int p = 0; p < 4; p++)
                bp[p] = *reinterpret_cast<const u64*>(&Bs[k][2 * tc + 32 * p]);
#pragma unroll
            for (int i = 0; i < 4; i++)
#pragma unroll
                for (int p = 0; p < 4; p++) ffma2(acc[i][p], ap[i], bp[p]);
        }
    }
#pragma unroll
    for (int i = 0; i < 4; i++) {
        const int m = tr + 16 * i;
#pragma unroll
        for (int p = 0; p < 4; p++) {
            const int c = 2 * tc + 32 * p;
            float x, y; unpack2(acc[i][p], x, y);
            g_svp[kc][(size_t)(b * MSLOT + m) * DSZ + d0 + c]     = x;
            g_svp[kc][(size_t)(b * MSLOT + m) * DSZ + d0 + c + 1] = y;
        }
    }
}

// ---------------- K6: slot_o = sv @ o_w^T (FFMA2); sv computed inline from svp ----
__global__ __launch_bounds__(256) void k_so(const float* __restrict__ o_w,
                                            const float* __restrict__ v_b) {
    __shared__ float Asd[16][136];
    __shared__ float Bs[16][136];
    const int tid = threadIdx.x;
    const int h0 = blockIdx.x * 128;
    const int b = blockIdx.y;
    const int tr = tid >> 4, tc = tid & 15;

    u64 acc[4][4];
#pragma unroll
    for (int i = 0; i < 4; i++)
#pragma unroll
        for (int p = 0; p < 4; p++) acc[i][p] = 0ull;

    for (int k0 = 0; k0 < DSZ; k0 += 16) {
        __syncthreads();
        {
            const int m = tid >> 2, kq = (tid & 3) << 2;
            const size_t off = (size_t)(b * MSLOT + m) * DSZ + k0 + kq;
            float4 va = *reinterpret_cast<const float4*>(&g_svp[0][off]);
#pragma unroll
            for (int c = 1; c < 8; c++) {
                const float4 vp = *reinterpret_cast<const float4*>(&g_svp[c][off]);
                va.x += vp.x; va.y += vp.y; va.z += vp.z; va.w += vp.w;
            }
            const float sbm = g_S[b * MSLOT + m];
            const float4 vb4 = *reinterpret_cast<const float4*>(&v_b[k0 + kq]);
            va.x += sbm * vb4.x; va.y += sbm * vb4.y;
            va.z += sbm * vb4.z; va.w += sbm * vb4.w;
            *reinterpret_cast<u64*>(&Asd[kq + 0][2 * m]) = pack2(va.x, va.x);
            *reinterpret_cast<u64*>(&Asd[kq + 1][2 * m]) = pack2(va.y, va.y);
            *reinterpret_cast<u64*>(&Asd[kq + 2][2 * m]) = pack2(va.z, va.z);
            *reinterpret_cast<u64*>(&Asd[kq + 3][2 * m]) = pack2(va.w, va.w);
        }
#pragma unroll
        for (int i = 0; i < 2; i++) {
            const int idx = tid + i * 256;
            const int c = idx >> 2, kq = (idx & 3) << 2;
            const float4 vb = *reinterpret_cast<const float4*>(
                &o_w[(size_t)(h0 + c) * DSZ + k0 + kq]);
            Bs[kq + 0][c] = vb.x; Bs[kq + 1][c] = vb.y;
            Bs[kq + 2][c] = vb.z; Bs[kq + 3][c] = vb.w;
        }
        __syncthreads();
#pragma unroll
        for (int k = 0; k < 16; k++) {
            u64 ap[4], bp[4];
#pragma unroll
            for (int i = 0; i < 4; i++)
                ap[i] = *reinterpret_cast<const u64*>(&Asd[k][2 * (tr + 16 * i)]);
#pragma unroll
            for (int p = 0; p < 4; p++)
                bp[p] = *reinterpret_cast<const u64*>(&Bs[k][2 * tc + 32 * p]);
#pragma unroll
            for (int i = 0; i < 4; i++)
#pragma unroll
                for (int p = 0; p < 4; p++) ffma2(acc[i][p], ap[i], bp[p]);
        }
    }
#pragma unroll
    for (int i = 0; i < 4; i++) {
        const int m = tr + 16 * i;
#pragma unroll
        for (int p = 0; p < 4; p++) {
            const int c = 2 * tc + 32 * p;
            float x, y; unpack2(acc[i][p], x, y);
            g_so[(size_t)(b * MSLOT + m) * HID + h0 + c]     = x;
            g_so[(size_t)(b * MSLOT + m) * HID + h0 + c + 1] = y;
        }
    }
}

// ---------------- K7: out = gates @ slot_o + o_b via HMMA (x4-paired B, 2 CTA/SM) ----
#define FSA 72
#define FSB 136
#define FSM_BYTES (2 * 128 * FSA * 2 + 2 * 64 * FSB * 2)   // 71680

__global__ __launch_bounds__(256, 2) void k_final_h(const float* __restrict__ gates,
                                                    const float* __restrict__ o_b,
                                                    float* __restrict__ out) {
    extern __shared__ unsigned short fs[];
    unsigned short* Ah = fs;
    unsigned short* Al = Ah + 128 * FSA;
    unsigned short* Bh = Al + 128 * FSA;
    unsigned short* Bl = Bh + 64 * FSB;
    const uint32_t ah_u = smem_u32(Ah), al_u = smem_u32(Al);
    const uint32_t bh_u = smem_u32(Bh), bl_u = smem_u32(Bl);

    const int tid = threadIdx.x, wid = tid >> 5, lane = tid & 31;
    const int n0 = blockIdx.x * 128, h0 = blockIdx.y * 128;
    const int b = n0 >> 12;
    const int wm = wid >> 2, wn = wid & 3;

#pragma unroll
    for (int t = 0; t < 8; t++) {
        const int idx = tid + t * 256;
        const int r = idx >> 4, mq = (idx & 15) * 4;
        const float4 v = *reinterpret_cast<const float4*>(
            &gates[(size_t)(n0 + r) * MSLOT + mq]);
        split4(Ah, Al, r * FSA + mq, v);
    }
#pragma unroll
    for (int t = 0; t < 8; t++) {
        const int idx = tid + t * 256;
        const int m = idx >> 5, hq = (idx & 31) * 4;
        const float4 v = *reinterpret_cast<const float4*>(
            &g_so[((size_t)(b * MSLOT + m)) * HID + h0 + hq]);
        split4(Bh, Bl, m * FSB + hq, v);
    }
    __syncthreads();

    float acc[4][4][4];
#pragma unroll
    for (int i = 0; i < 4; i++)
#pragma unroll
        for (int j = 0; j < 4; j++)
#pragma unroll
            for (int f = 0; f < 4; f++) acc[i][j][f] = 0.f;

#pragma unroll
    for (int kk = 0; kk < 64; kk += 16) {
        uint32_t bhf[4][2], blf[4][2];
        const int krow = kk + ((lane >> 3) & 1) * 8 + (lane & 7);
        const int cadd = (lane >> 4) * 8;
#pragma unroll
        for (int np = 0; np < 2; np++) {
            const int bcol = wn * 32 + np * 16 + cadd;
            const uint32_t off = (uint32_t)(krow * FSB + bcol) * 2;
            ldsm_x4_t(bhf[2 * np][0], bhf[2 * np][1], bhf[2 * np + 1][0], bhf[2 * np + 1][1],
                      bh_u + off);
            ldsm_x4_t(blf[2 * np][0], blf[2 * np][1], blf[2 * np + 1][0], blf[2 * np + 1][1],
                      bl_u + off);
        }
#pragma unroll
        for (int mi = 0; mi < 4; mi++) {
            const int arow = wm * 64 + mi * 16 + (lane & 15);
            const int acol = kk + (lane >> 4) * 8;
            const uint32_t off = (arow * FSA + acol) * 2;
            uint32_t ahf[4], alf[4];
            ldsm_x4(ahf[0], ahf[1], ahf[2], ahf[3], ah_u + off);
            ldsm_x4(alf[0], alf[1], alf[2], alf[3], al_u + off);
#pragma unroll
            for (int ni = 0; ni < 4; ni++) {
                mma_bf16(acc[mi][ni], ahf, bhf[ni]);
                mma_bf16(acc[mi][ni], ahf, blf[ni]);
                mma_bf16(acc[mi][ni], alf, bhf[ni]);
            }
        }
    }

    const int qr = lane >> 2, qc = (lane & 3) * 2;
#pragma unroll
    for (int mi = 0; mi < 4; mi++) {
        const int n = n0 + wm * 64 + mi * 16 + qr;
#pragma unroll
        for (int ni = 0; ni < 4; ni++) {
            const int h = h0 + wn * 32 + ni * 8 + qc;
            const float b0 = o_b[h], b1 = o_b[h + 1];
            *reinterpret_cast<float2*>(&out[(size_t)n * HID + h]) =
                make_float2(acc[mi][ni][0] + b0, acc[mi][ni][1] + b1);
            *reinterpret_cast<float2*>(&out[(size_t)(n + 8) * HID + h]) =
                make_float2(acc[mi][ni][2] + b0, acc[mi][ni][3] + b1);
        }
    }
}

// ---------------- launch ----------------
extern "C" void kernel_launch(void* const* d_in, const int* in_sizes, int n_in,
                              void* d_out, int out_size) {
    const float* hs     = (const float*)d_in[0];
    const float* slots  = (const float*)d_in[2];
    const float* q_w    = (const float*)d_in[3];
    const float* q_b    = (const float*)d_in[4];
    const float* v_w    = (const float*)d_in[7];
    const float* v_b    = (const float*)d_in[8];
    const float* gate_w = (const float*)d_in[9];
    const float* gate_b = (const float*)d_in[10];
    const float* o_w    = (const float*)d_in[11];
    const float* o_b    = (const float*)d_in[12];

    float* out       = (float*)d_out;
    float* gates_out = out + (size_t)BNTOK * HID;

    cudaFuncSetAttribute(k_logits_f, cudaFuncAttributeMaxDynamicSharedMemorySize, LG_SMEM);
    cudaFuncSetAttribute(k_X_h, cudaFuncAttributeMaxDynamicSharedMemorySize, XSM_BYTES);
    cudaFuncSetAttribute(k_final_h, cudaFuncAttributeMaxDynamicSharedMemorySize, FSM_BYTES);

    k_prep     <<<dim3(HID / 128, 6), 128>>>(slots, q_w, q_b, gate_w);
    k_logits_f <<<BNTOK / 128, 512, LG_SMEM>>>(hs, gate_b, gates_out);
    k_X_h      <<<dim3(HID / 128, BATCH, NXC), 256, XSM_BYTES>>>(hs);
    k_sv       <<<dim3(2, BATCH, 8), 256>>>(v_w);
    k_so       <<<dim3(HID / 128, BATCH), 256>>>(o_w, v_b);
    k_final_h  <<<dim3(BNTOK / 128, HID / 128), 256, FSM_BYTES>>>(gates_out, o_b, out);
}

// round 16
// speedup vs baseline: 1.0713x; 1.0713x over previous
#include <cuda_runtime.h>
#include <cuda_bf16.h>
#include <cstddef>
#include <cstdint>

// ---------------- problem constants ----------------
#define HID   4096
#define DSZ   256
#define MSLOT 64
#define BATCH 4
#define NTOK  4096
#define BNTOK (BATCH * NTOK)
#define LCOLS 128
#define NXC   4
#define KSP   16                 // k_sv K-split chunks (256 wide each)

typedef unsigned long long u64;

// ---------------- packed fp32x2 helpers ----------------
__device__ __forceinline__ u64 pack2(float x, float y) {
    u64 r; asm("mov.b64 %0, {%1, %2};" : "=l"(r) : "f"(x), "f"(y)); return r;
}
__device__ __forceinline__ void unpack2(u64 v, float& x, float& y) {
    asm("mov.b64 {%0, %1}, %2;" : "=f"(x), "=f"(y) : "l"(v));
}
__device__ __forceinline__ void ffma2(u64& d, u64 a, u64 b) {
    asm("fma.rn.f32x2 %0, %1, %2, %0;" : "+l"(d) : "l"(a), "l"(b));
}
__device__ __forceinline__ uint32_t smem_u32(const void* p) {
    uint32_t a;
    asm("{ .reg .u64 t; cvta.to.shared.u64 t, %1; cvt.u32.u64 %0, t; }" : "=r"(a) : "l"(p));
    return a;
}

// ---------------- cp.async helpers ----------------
__device__ __forceinline__ void cp_async16(uint32_t dst, const void* src) {
    asm volatile("cp.async.cg.shared.global [%0], [%1], 16;" :: "r"(dst), "l"(src));
}
#define CP_COMMIT() asm volatile("cp.async.commit_group;" ::: "memory")
#define CP_WAIT0()  asm volatile("cp.async.wait_group 0;" ::: "memory")

// ---------------- mma.sync helpers ----------------
__device__ __forceinline__ void ldsm_x4(uint32_t& a0, uint32_t& a1, uint32_t& a2, uint32_t& a3,
                                        uint32_t addr) {
    asm volatile("ldmatrix.sync.aligned.m8n8.x4.shared.b16 {%0,%1,%2,%3}, [%4];"
                 : "=r"(a0), "=r"(a1), "=r"(a2), "=r"(a3) : "r"(addr));
}
__device__ __forceinline__ void ldsm_x4_t(uint32_t& a0, uint32_t& a1, uint32_t& a2, uint32_t& a3,
                                          uint32_t addr) {
    asm volatile("ldmatrix.sync.aligned.m8n8.x4.trans.shared.b16 {%0,%1,%2,%3}, [%4];"
                 : "=r"(a0), "=r"(a1), "=r"(a2), "=r"(a3) : "r"(addr));
}
__device__ __forceinline__ void mma_bf16(float* d, const uint32_t* a, const uint32_t* b) {
    asm volatile("mma.sync.aligned.m16n8k16.row.col.f32.bf16.bf16.f32 "
                 "{%0,%1,%2,%3}, {%4,%5,%6,%7}, {%8,%9}, {%0,%1,%2,%3};"
                 : "+f"(d[0]), "+f"(d[1]), "+f"(d[2]), "+f"(d[3])
                 : "r"(a[0]), "r"(a[1]), "r"(a[2]), "r"(a[3]), "r"(b[0]), "r"(b[1]));
}

__device__ __forceinline__ void split4(unsigned short* Hi, unsigned short* Lo,
                                       size_t off, float4 v) {
    __nv_bfloat16 h0 = __float2bfloat16_rn(v.x), h1 = __float2bfloat16_rn(v.y);
    __nv_bfloat16 h2 = __float2bfloat16_rn(v.z), h3 = __float2bfloat16_rn(v.w);
    __nv_bfloat16 l0 = __float2bfloat16_rn(v.x - __bfloat162float(h0));
    __nv_bfloat16 l1 = __float2bfloat16_rn(v.y - __bfloat162float(h1));
    __nv_bfloat16 l2 = __float2bfloat16_rn(v.z - __bfloat162float(h2));
    __nv_bfloat16 l3 = __float2bfloat16_rn(v.w - __bfloat162float(h3));
    *reinterpret_cast<ushort4*>(&Hi[off]) =
        make_ushort4(__bfloat16_as_ushort(h0), __bfloat16_as_ushort(h1),
                     __bfloat16_as_ushort(h2), __bfloat16_as_ushort(h3));
    *reinterpret_cast<ushort4*>(&Lo[off]) =
        make_ushort4(__bfloat16_as_ushort(l0), __bfloat16_as_ushort(l1),
                     __bfloat16_as_ushort(l2), __bfloat16_as_ushort(l3));
}

// ---------------- scratch ----------------
__device__ __nv_bfloat16 g_wh[LCOLS * HID];
__device__ __nv_bfloat16 g_wl[LCOLS * HID];
__device__ float g_qsb[MSLOT];
__device__ __nv_bfloat16 g_swh[(size_t)BNTOK * MSLOT];
__device__ __nv_bfloat16 g_swl[(size_t)BNTOK * MSLOT];
__device__ float g_S[BATCH * MSLOT];
__device__ float g_Xp[NXC][BATCH * MSLOT * HID];
__device__ float g_svp[KSP][BATCH * MSLOT * DSZ];
__device__ float g_so[BATCH * MSLOT * HID];

// ---------------- K1: qs_w rows -> g_wh/g_wl[64..127], qsb, zero g_S ----------------
__global__ __launch_bounds__(128) void k_qsw(const float* __restrict__ slots,
                                             const float* __restrict__ q_w,
                                             const float* __restrict__ q_b) {
    __shared__ float s_slot[16 * DSZ];
    const int mg = blockIdx.y * 16;
    const int h  = blockIdx.x * 128 + threadIdx.x;
#pragma unroll
    for (int j = 0; j < 8; j++) {
        const int idx = threadIdx.x + j * 128;
        const int mm = idx >> 6, dq = (idx & 63) << 2;
        *reinterpret_cast<float4*>(&s_slot[mm * DSZ + dq]) =
            *reinterpret_cast<const float4*>(&slots[(size_t)(mg + mm) * DSZ + dq]);
    }
    __syncthreads();
    float acc[16];
#pragma unroll
    for (int i = 0; i < 16; i++) acc[i] = 0.f;
    for (int d = 0; d < DSZ; d++) {
        const float w = q_w[(size_t)d * HID + h];
#pragma unroll
        for (int i = 0; i < 16; i++) acc[i] += s_slot[i * DSZ + d] * w;
    }
#pragma unroll
    for (int i = 0; i < 16; i++) {
        const __nv_bfloat16 hi = __float2bfloat16_rn(acc[i]);
        const __nv_bfloat16 lo = __float2bfloat16_rn(acc[i] - __bfloat162float(hi));
        g_wh[(size_t)(64 + mg + i) * HID + h] = hi;
        g_wl[(size_t)(64 + mg + i) * HID + h] = lo;
    }
    if (blockIdx.x == 0 && blockIdx.y == 0) {
        g_S[threadIdx.x] = 0.f;
        g_S[threadIdx.x + 128] = 0.f;
        if (threadIdx.x < MSLOT) {
            float b = 0.f;
            for (int d = 0; d < DSZ; d++) b += slots[(size_t)threadIdx.x * DSZ + d] * q_b[d];
            g_qsb[threadIdx.x] = b;
        }
    }
}

// ---------------- K1b: gate_w -> g_wh/g_wl[0..63] ----------------
__global__ __launch_bounds__(256) void k_wg(const float* __restrict__ gw) {
    const int idx = blockIdx.x * 256 + threadIdx.x;
    const int r = idx >> 10, q = (idx & 1023) << 2;
    const float4 v = *reinterpret_cast<const float4*>(&gw[(size_t)r * HID + q]);
    split4(reinterpret_cast<unsigned short*>(g_wh),
           reinterpret_cast<unsigned short*>(g_wl), (size_t)r * HID + q, v);
}

// ---------------- K2: fused logits GEMM + dual softmax (R14-proven M128) ----
#define KC  32
#define SH  40
#define NCH (HID / KC)            // 128
#define LTA (128 * SH)            // 5120 halfs per tile
#define LST (4 * LTA)             // stage = 20480 halfs
#define LG_SMEM (2 * LST * 2)     // 81920 bytes

__global__ __launch_bounds__(512) void k_logits_f(const float* __restrict__ hs,
                                                  const float* __restrict__ gb,
                                                  float* __restrict__ gates_out) {
    extern __shared__ __align__(16) unsigned short ls[];
    const int tid = threadIdx.x;
    const int wid = tid >> 5, lane = tid & 31;
    const int row0 = blockIdx.x * 128;
    const int wm = wid >> 2, wn = wid & 3;
    const uint32_t base_u = smem_u32(ls);

    float acc[2][4][4];
#pragma unroll
    for (int i = 0; i < 2; i++)
#pragma unroll
        for (int j = 0; j < 4; j++)
#pragma unroll
            for (int f = 0; f < 4; f++) acc[i][j][f] = 0.f;

    float4 ar[2];
#pragma unroll
    for (int t = 0; t < 2; t++) {
        const int idx = tid + t * 512;
        const int hf = idx >> 9, rem = idx & 511;
        const int r = rem >> 2, q = rem & 3;
        const __nv_bfloat16* src = (hf ? g_wl : g_wh) + (size_t)r * HID + q * 8;
        cp_async16(base_u + (uint32_t)((2 + hf) * LTA + r * SH + q * 8) * 2, src);
    }
    CP_COMMIT();
#pragma unroll
    for (int t = 0; t < 2; t++) {
        const int idx = tid + t * 512, r = idx >> 3, q = idx & 7;
        ar[t] = *reinterpret_cast<const float4*>(&hs[(size_t)(row0 + r) * HID + q * 4]);
    }
#pragma unroll
    for (int t = 0; t < 2; t++) {
        const int idx = tid + t * 512, r = idx >> 3, q = idx & 7;
        split4(ls, ls + LTA, r * SH + q * 4, ar[t]);
    }
#pragma unroll
    for (int t = 0; t < 2; t++) {
        const int idx = tid + t * 512, r = idx >> 3, q = idx & 7;
        ar[t] = *reinterpret_cast<const float4*>(&hs[(size_t)(row0 + r) * HID + KC + q * 4]);
    }

    auto kstep = [&](uint32_t ah_u, uint32_t al_u, uint32_t bh_u, uint32_t bl_u, int kk) {
        uint32_t bhf[4][2], blf[4][2];
        const int nrow = (lane >> 4) * 8 + (lane & 7);
        const int bcol = kk + ((lane >> 3) & 1) * 8;
#pragma unroll
        for (int np = 0; np < 2; np++) {
            const int brow = wn * 32 + np * 16 + nrow;
            const uint32_t off = (uint32_t)(brow * SH + bcol) * 2;
            ldsm_x4(bhf[2 * np][0], bhf[2 * np][1], bhf[2 * np + 1][0], bhf[2 * np + 1][1],
                    bh_u + off);
            ldsm_x4(blf[2 * np][0], blf[2 * np][1], blf[2 * np + 1][0], blf[2 * np + 1][1],
                    bl_u + off);
        }
#pragma unroll
        for (int mi = 0; mi < 2; mi++) {
            const int arow = wm * 32 + mi * 16 + (lane & 15);
            const int acol = kk + (lane >> 4) * 8;
            const uint32_t off = (uint32_t)(arow * SH + acol) * 2;
            uint32_t ahf[4], alf[4];
            ldsm_x4(ahf[0], ahf[1], ahf[2], ahf[3], ah_u + off);
            ldsm_x4(alf[0], alf[1], alf[2], alf[3], al_u + off);
#pragma unroll
            for (int ni = 0; ni < 4; ni++) {
                mma_bf16(acc[mi][ni], ahf, bhf[ni]);
                mma_bf16(acc[mi][ni], ahf, blf[ni]);
                mma_bf16(acc[mi][ni], alf, bhf[ni]);
            }
        }
    };

    for (int c = 0; c < NCH; c++) {
        const int s = c & 1;
        CP_WAIT0();
        __syncthreads();
        if (c + 1 < NCH) {
            const int k0 = (c + 1) * KC;
            const uint32_t st1 = (uint32_t)((s ^ 1) * LST);
#pragma unroll
            for (int t = 0; t < 2; t++) {
                const int idx = tid + t * 512;
                const int hf = idx >> 9, rem = idx & 511;
                const int r = rem >> 2, q = rem & 3;
                const __nv_bfloat16* src = (hf ? g_wl : g_wh) + (size_t)r * HID + k0 + q * 8;
                cp_async16(base_u + (st1 + (2 + hf) * LTA + r * SH + q * 8) * 2, src);
            }
            CP_COMMIT();
        }
        const uint32_t ah_u = base_u + (uint32_t)(s * LST) * 2;
        const uint32_t al_u = ah_u + LTA * 2;
        const uint32_t bh_u = ah_u + 2 * LTA * 2;
        const uint32_t bl_u = ah_u + 3 * LTA * 2;

        kstep(ah_u, al_u, bh_u, bl_u, 0);
        if (c + 1 < NCH) {
            unsigned short* Ah1 = ls + (s ^ 1) * LST;
#pragma unroll
            for (int t = 0; t < 2; t++) {
                const int idx = tid + t * 512, r = idx >> 3, q = idx & 7;
                split4(Ah1, Ah1 + LTA, r * SH + q * 4, ar[t]);
            }
            if (c + 2 < NCH) {
                const int k2 = (c + 2) * KC;
#pragma unroll
                for (int t = 0; t < 2; t++) {
                    const int idx = tid + t * 512, r = idx >> 3, q = idx & 7;
                    ar[t] = *reinterpret_cast<const float4*>(
                        &hs[(size_t)(row0 + r) * HID + k2 + q * 4]);
                }
            }
        }
        kstep(ah_u, al_u, bh_u, bl_u, 16);
    }

    __syncthreads();
    float* sl = reinterpret_cast<float*>(ls);
    const int qr = lane >> 2, qc = (lane & 3) * 2;
#pragma unroll
    for (int mi = 0; mi < 2; mi++) {
        const int lr = wm * 32 + mi * 16 + qr;
#pragma unroll
        for (int ni = 0; ni < 4; ni++) {
            const int c0 = wn * 32 + ni * 8 + qc;
            const float b0 = (c0 < 64) ? gb[c0] : g_qsb[c0 - 64];
            const float b1 = (c0 + 1 < 64) ? gb[c0 + 1] : g_qsb[c0 + 1 - 64];
            sl[lr * 132 + c0]           = acc[mi][ni][0] + b0;
            sl[lr * 132 + c0 + 1]       = acc[mi][ni][1] + b1;
            sl[(lr + 8) * 132 + c0]     = acc[mi][ni][2] + b0;
            sl[(lr + 8) * 132 + c0 + 1] = acc[mi][ni][3] + b1;
        }
    }
    __syncthreads();

    const int b = row0 >> 12;
    float s0 = 0.f, s1 = 0.f;
#pragma unroll
    for (int rr = 0; rr < 8; rr++) {
        const int row = wid * 8 + rr;
        const size_t n = row0 + row;
        const float* rp = sl + row * 132;
        {
            float g0 = rp[lane], g1 = rp[32 + lane];
            float mx = fmaxf(g0, g1);
#pragma unroll
            for (int o = 16; o; o >>= 1) mx = fmaxf(mx, __shfl_xor_sync(0xffffffffu, mx, o));
            float e0 = __expf(g0 - mx), e1 = __expf(g1 - mx);
            float ss = e0 + e1;
#pragma unroll
            for (int o = 16; o; o >>= 1) ss += __shfl_xor_sync(0xffffffffu, ss, o);
            const float inv = 1.f / ss;
            gates_out[n * MSLOT + lane]      = e0 * inv;
            gates_out[n * MSLOT + 32 + lane] = e1 * inv;
        }
        {
            float g0 = rp[64 + lane], g1 = rp[96 + lane];
            float mx = fmaxf(g0, g1);
#pragma unroll
            for (int o = 16; o; o >>= 1) mx = fmaxf(mx, __shfl_xor_sync(0xffffffffu, mx, o));
            float e0 = __expf(g0 - mx), e1 = __expf(g1 - mx);
            float ss = e0 + e1;
#pragma unroll
            for (int o = 16; o; o >>= 1) ss += __shfl_xor_sync(0xffffffffu, ss, o);
            const float inv = 1.f / ss;
            const float w0 = e0 * inv, w1 = e1 * inv;
            const __nv_bfloat16 h0 = __float2bfloat16_rn(w0);
            const __nv_bfloat16 h1 = __float2bfloat16_rn(w1);
            g_swh[n * MSLOT + lane]      = h0;
            g_swh[n * MSLOT + 32 + lane] = h1;
            g_swl[n * MSLOT + lane]      = __float2bfloat16_rn(w0 - __bfloat162float(h0));
            g_swl[n * MSLOT + 32 + lane] = __float2bfloat16_rn(w1 - __bfloat162float(h1));
            s0 += w0; s1 += w1;
        }
    }
    atomicAdd(&g_S[b * MSLOT + lane], s0);
    atomicAdd(&g_S[b * MSLOT + 32 + lane], s1);
}

// ---------------- K4: X partials — x4-paired B loads, 3 CTAs/SM (R14-proven) ----
#define XSA 72
#define XSB 136
#define TB  32
#define XT_A (TB * XSA)
#define XT_B (TB * XSB)
#define X_STAGE (2 * XT_A + 2 * XT_B)            // 13312 halfs
#define XSM_BYTES (2 * X_STAGE * 2)              // 53248 bytes
#define XITS (1024 / TB)                         // 32

__global__ __launch_bounds__(256, 3) void k_X_h(const float* __restrict__ hs) {
    extern __shared__ __align__(16) unsigned short xs[];
    const int tid = threadIdx.x, wid = tid >> 5, lane = tid & 31;
    const int h0 = blockIdx.x * 128, b = blockIdx.y, nc = blockIdx.z;
    const int wm = wid >> 2, wn = wid & 3;
    const uint32_t base_u = smem_u32(xs);
    const int A_OFF = 0, AL_OFF = XT_A, BH_OFF = 2 * XT_A, BL_OFF = 2 * XT_A + XT_B;
    const int nbase = nc * 1024;

    float acc[2][4][4];
#pragma unroll
    for (int i = 0; i < 2; i++)
#pragma unroll
        for (int j = 0; j < 4; j++)
#pragma unroll
            for (int f = 0; f < 4; f++) acc[i][j][f] = 0.f;

    float4 br[4];
#pragma unroll
    for (int t = 0; t < 2; t++) {
        const int idx = tid + t * 256;
        const int hf = idx >> 8, rem = idx & 255;
        const int r = rem >> 3, q = rem & 7;
        const __nv_bfloat16* src = (hf ? g_swl : g_swh) +
            ((size_t)(b * NTOK + nbase + r)) * MSLOT + q * 8;
        cp_async16(base_u + (uint32_t)((hf ? AL_OFF : A_OFF) + r * XSA + q * 8) * 2, src);
    }
    CP_COMMIT();
#pragma unroll
    for (int t = 0; t < 4; t++) {
        const int idx = tid + t * 256;
        const int n = idx >> 5, hq = (idx & 31) * 4;
        br[t] = *reinterpret_cast<const float4*>(
            &hs[((size_t)(b * NTOK + nbase + n)) * HID + h0 + hq]);
    }
#pragma unroll
    for (int t = 0; t < 4; t++) {
        const int idx = tid + t * 256;
        const int n = idx >> 5, hq = (idx & 31) * 4;
        split4(xs + BH_OFF, xs + BL_OFF, n * XSB + hq, br[t]);
    }

    auto kstep = [&](uint32_t ah_u, uint32_t al_u, uint32_t bh_u, uint32_t bl_u, int kk) {
        uint32_t bhf[4][2], blf[4][2];
        const int krow = kk + ((lane >> 3) & 1) * 8 + (lane & 7);
        const int cadd = (lane >> 4) * 8;
#pragma unroll
        for (int np = 0; np < 2; np++) {
            const int bcol = wn * 32 + np * 16 + cadd;
            const uint32_t off = (uint32_t)(krow * XSB + bcol) * 2;
            ldsm_x4_t(bhf[2 * np][0], bhf[2 * np][1], bhf[2 * np + 1][0], bhf[2 * np + 1][1],
                      bh_u + off);
            ldsm_x4_t(blf[2 * np][0], blf[2 * np][1], blf[2 * np + 1][0], blf[2 * np + 1][1],
                      bl_u + off);
        }
        const int arow = kk + ((lane >> 4) & 1) * 8 + (lane & 7);
        const int acsel = ((lane >> 3) & 1) * 8;
#pragma unroll
        for (int mi = 0; mi < 2; mi++) {
            const int acol = wm * 32 + mi * 16 + acsel;
            const uint32_t off = (uint32_t)(arow * XSA + acol) * 2;
            uint32_t ahf[4], alf[4];
            ldsm_x4_t(ahf[0], ahf[1], ahf[2], ahf[3], ah_u + off);
            ldsm_x4_t(alf[0], alf[1], alf[2], alf[3], al_u + off);
#pragma unroll
            for (int ni = 0; ni < 4; ni++) {
                mma_bf16(acc[mi][ni], ahf, bhf[ni]);
                mma_bf16(acc[mi][ni], ahf, blf[ni]);
                mma_bf16(acc[mi][ni], alf, bhf[ni]);
            }
        }
    };

    for (int it = 0; it < XITS; it++) {
        const int s = it & 1;
        CP_WAIT0();
        __syncthreads();
        if (it + 1 < XITS) {
            const int n0 = nbase + (it + 1) * TB;
#pragma unroll
            for (int t = 0; t < 4; t++) {
                const int idx = tid + t * 256;
                const int n = idx >> 5, hq = (idx & 31) * 4;
                br[t] = *reinterpret_cast<const float4*>(
                    &hs[((size_t)(b * NTOK + n0 + n)) * HID + h0 + hq]);
            }
            const uint32_t st1 = (uint32_t)((s ^ 1) * X_STAGE);
#pragma unroll
            for (int t = 0; t < 2; t++) {
                const int idx = tid + t * 256;
                const int hf = idx >> 8, rem = idx & 255;
                const int r = rem >> 3, q = rem & 7;
                const __nv_bfloat16* src = (hf ? g_swl : g_swh) +
                    ((size_t)(b * NTOK + n0 + r)) * MSLOT + q * 8;
                cp_async16(base_u + (st1 + (hf ? AL_OFF : A_OFF) + r * XSA + q * 8) * 2, src);
            }
            CP_COMMIT();
        }
        const uint32_t ah_u = base_u + (uint32_t)(s * X_STAGE + A_OFF) * 2;
        const uint32_t al_u = base_u + (uint32_t)(s * X_STAGE + AL_OFF) * 2;
        const uint32_t bh_u = base_u + (uint32_t)(s * X_STAGE + BH_OFF) * 2;
        const uint32_t bl_u = base_u + (uint32_t)(s * X_STAGE + BL_OFF) * 2;

        kstep(ah_u, al_u, bh_u, bl_u, 0);
        kstep(ah_u, al_u, bh_u, bl_u, 16);
        if (it + 1 < XITS) {
            unsigned short* Bh1 = xs + (s ^ 1) * X_STAGE + BH_OFF;
            unsigned short* Bl1 = xs + (s ^ 1) * X_STAGE + BL_OFF;
#pragma unroll
            for (int t = 0; t < 4; t++) {
                const int idx = tid + t * 256;
                const int n = idx >> 5, hq = (idx & 31) * 4;
                split4(Bh1, Bl1, n * XSB + hq, br[t]);
            }
        }
    }

    const int qr = lane >> 2, qc = (lane & 3) * 2;
#pragma unroll
    for (int mi = 0; mi < 2; mi++) {
        const int m = wm * 32 + mi * 16 + qr;
#pragma unroll
        for (int ni = 0; ni < 4; ni++) {
            const int h = h0 + wn * 32 + ni * 8 + qc;
            *reinterpret_cast<float2*>(
                &g_Xp[nc][((size_t)(b * MSLOT + m)) * HID + h]) =
                make_float2(acc[mi][ni][0], acc[mi][ni][1]);
            *reinterpret_cast<float2*>(
                &g_Xp[nc][((size_t)(b * MSLOT + m + 8)) * HID + h]) =
                make_float2(acc[mi][ni][2], acc[mi][ni][3]);
        }
    }
}

// ---------------- K5: sv partials (FFMA2), 256-wide K chunks, 128 CTAs ----------------
__global__ __launch_bounds__(256) void k_sv(const float* __restrict__ v_w) {
    __shared__ float Asd[16][136];
    __shared__ float Bs[16][136];
    const int tid = threadIdx.x;
    const int d0 = blockIdx.x * 128;
    const int b = blockIdx.y;
    const int kc = blockIdx.z;                // 0..KSP-1, 256-wide chunks
    const int tr = tid >> 4, tc = tid & 15;

    u64 acc[4][4];
#pragma unroll
    for (int i = 0; i < 4; i++)
#pragma unroll
        for (int p = 0; p < 4; p++) acc[i][p] = 0ull;

    const int kbeg = kc * (HID / KSP);
    const int kend = kbeg + (HID / KSP);      // 256 wide
    for (int k0 = kbeg; k0 < kend; k0 += 16) {
        __syncthreads();
        {
            const int m = tid >> 2, kq = (tid & 3) << 2;
            const size_t off = ((size_t)(b * MSLOT + m)) * HID + k0 + kq;
            float4 va = *reinterpret_cast<const float4*>(&g_Xp[0][off]);
#pragma unroll
            for (int c = 1; c < NXC; c++) {
                const float4 vp = *reinterpret_cast<const float4*>(&g_Xp[c][off]);
                va.x += vp.x; va.y += vp.y; va.z += vp.z; va.w += vp.w;
            }
            *reinterpret_cast<u64*>(&Asd[kq + 0][2 * m]) = pack2(va.x, va.x);
            *reinterpret_cast<u64*>(&Asd[kq + 1][2 * m]) = pack2(va.y, va.y);
            *reinterpret_cast<u64*>(&Asd[kq + 2][2 * m]) = pack2(va.z, va.z);
            *reinterpret_cast<u64*>(&Asd[kq + 3][2 * m]) = pack2(va.w, va.w);
        }
#pragma unroll
        for (int i = 0; i < 2; i++) {
            const int idx = tid + i * 256;
            const int c = idx >> 2, kq = (idx & 3) << 2;
            const float4 vb = *reinterpret_cast<const float4*>(
                &v_w[(size_t)(d0 + c) * HID + k0 + kq]);
            Bs[kq + 0][c] = vb.x; Bs[kq + 1][c] = vb.y;
            Bs[kq + 2][c] = vb.z; Bs[kq + 3][c] = vb.w;
        }
        __syncthreads();
#pragma unroll
        for (int k = 0; k < 16; k++) {
            u64 ap[4], bp[4];
#pragma unroll
            for (int i = 0; i < 4; i++)
                ap[i] = *reinterpret_cast<const u64*>(&Asd[k][2 * (tr + 16 * i)]);
#pragma unroll
            for (int p = 0; p < 4; p++)
                bp[p] = *reinterpret_cast<const u64*>(&Bs[k][2 * tc + 32 * p]);
#pragma unroll
            for (int i = 0; i < 4; i++)
#pragma unroll
                for (int p = 0; p < 4; p++) ffma2(acc[i][p], ap[i], bp[p]);
        }
    }
#pragma unroll
    for (int i = 0; i < 4; i++) {
        const int m = tr + 16 * i;
#pragma unroll
        for (int p = 0; p < 4; p++) {
            const int c = 2 * tc + 32 * p;
            float x, y; unpack2(acc[i][p], x, y);
            g_svp[kc][(size_t)(b * MSLOT + m) * DSZ + d0 + c]     = x;
            g_svp[kc][(size_t)(b * MSLOT + m) * DSZ + d0 + c + 1] = y;
        }
    }
}

// ---------------- K6: slot_o = sv @ o_w^T (FFMA2); sv computed inline from svp ----
__global__ __launch_bounds__(256) void k_so(const float* __restrict__ o_w,
                                            const float* __restrict__ v_b) {
    __shared__ float Asd[16][136];
    __shared__ float Bs[16][136];
    const int tid = threadIdx.x;
    const int h0 = blockIdx.x * 128;
    const int b = blockIdx.y;
    const int tr = tid >> 4, tc = tid & 15;

    u64 acc[4][4];
#pragma unroll
    for (int i = 0; i < 4; i++)
#pragma unroll
        for (int p = 0; p < 4; p++) acc[i][p] = 0ull;

    for (int k0 = 0; k0 < DSZ; k0 += 16) {
        __syncthreads();
        {
            const int m = tid >> 2, kq = (tid & 3) << 2;
            const size_t off = (size_t)(b * MSLOT + m) * DSZ + k0 + kq;
            float4 va = *reinterpret_cast<const float4*>(&g_svp[0][off]);
#pragma unroll
            for (int c = 1; c < KSP; c++) {
                const float4 vp = *reinterpret_cast<const float4*>(&g_svp[c][off]);
                va.x += vp.x; va.y += vp.y; va.z += vp.z; va.w += vp.w;
            }
            const float sbm = g_S[b * MSLOT + m];
            const float4 vb4 = *reinterpret_cast<const float4*>(&v_b[k0 + kq]);
            va.x += sbm * vb4.x; va.y += sbm * vb4.y;
            va.z += sbm * vb4.z; va.w += sbm * vb4.w;
            *reinterpret_cast<u64*>(&Asd[kq + 0][2 * m]) = pack2(va.x, va.x);
            *reinterpret_cast<u64*>(&Asd[kq + 1][2 * m]) = pack2(va.y, va.y);
            *reinterpret_cast<u64*>(&Asd[kq + 2][2 * m]) = pack2(va.z, va.z);
            *reinterpret_cast<u64*>(&Asd[kq + 3][2 * m]) = pack2(va.w, va.w);
        }
#pragma unroll
        for (int i = 0; i < 2; i++) {
            const int idx = tid + i * 256;
            const int c = idx >> 2, kq = (idx & 3) << 2;
            const float4 vb = *reinterpret_cast<const float4*>(
                &o_w[(size_t)(h0 + c) * DSZ + k0 + kq]);
            Bs[kq + 0][c] = vb.x; Bs[kq + 1][c] = vb.y;
            Bs[kq + 2][c] = vb.z; Bs[kq + 3][c] = vb.w;
        }
        __syncthreads();
#pragma unroll
        for (int k = 0; k < 16; k++) {
            u64 ap[4], bp[4];
#pragma unroll
            for (int i = 0; i < 4; i++)
                ap[i] = *reinterpret_cast<const u64*>(&Asd[k][2 * (tr + 16 * i)]);
#pragma unroll
            for (int p = 0; p < 4; p++)
                bp[p] = *reinterpret_cast<const u64*>(&Bs[k][2 * tc + 32 * p]);
#pragma unroll
            for (int i = 0; i < 4; i++)
#pragma unroll
                for (int p = 0; p < 4; p++) ffma2(acc[i][p], ap[i], bp[p]);
        }
    }
#pragma unroll
    for (int i = 0; i < 4; i++) {
        const int m = tr + 16 * i;
#pragma unroll
        for (int p = 0; p < 4; p++) {
            const int c = 2 * tc + 32 * p;
            float x, y; unpack2(acc[i][p], x, y);
            g_so[(size_t)(b * MSLOT + m) * HID + h0 + c]     = x;
            g_so[(size_t)(b * MSLOT + m) * HID + h0 + c + 1] = y;
        }
    }
}

// ---------------- K7: out = gates @ slot_o + o_b via HMMA (x4-paired B, 2 CTA/SM) ----
#define FSA 72
#define FSB 136
#define FSM_BYTES (2 * 128 * FSA * 2 + 2 * 64 * FSB * 2)   // 71680

__global__ __launch_bounds__(256, 2) void k_final_h(const float* __restrict__ gates,
                                                    const float* __restrict__ o_b,
                                                    float* __restrict__ out) {
    extern __shared__ unsigned short fs[];
    unsigned short* Ah = fs;
    unsigned short* Al = Ah + 128 * FSA;
    unsigned short* Bh = Al + 128 * FSA;
    unsigned short* Bl = Bh + 64 * FSB;
    const uint32_t ah_u = smem_u32(Ah), al_u = smem_u32(Al);
    const uint32_t bh_u = smem_u32(Bh), bl_u = smem_u32(Bl);

    const int tid = threadIdx.x, wid = tid >> 5, lane = tid & 31;
    const int n0 = blockIdx.x * 128, h0 = blockIdx.y * 128;
    const int b = n0 >> 12;
    const int wm = wid >> 2, wn = wid & 3;

#pragma unroll
    for (int t = 0; t < 8; t++) {
        const int idx = tid + t * 256;
        const int r = idx >> 4, mq = (idx & 15) * 4;
        const float4 v = *reinterpret_cast<const float4*>(
            &gates[(size_t)(n0 + r) * MSLOT + mq]);
        split4(Ah, Al, r * FSA + mq, v);
    }
#pragma unroll
    for (int t = 0; t < 8; t++) {
        const int idx = tid + t * 256;
        const int m = idx >> 5, hq = (idx & 31) * 4;
        const float4 v = *reinterpret_cast<const float4*>(
            &g_so[((size_t)(b * MSLOT + m)) * HID + h0 + hq]);
        split4(Bh, Bl, m * FSB + hq, v);
    }
    __syncthreads();

    float acc[4][4][4];
#pragma unroll
    for (int i = 0; i < 4; i++)
#pragma unroll
        for (int j = 0; j < 4; j++)
#pragma unroll
            for (int f = 0; f < 4; f++) acc[i][j][f] = 0.f;

#pragma unroll
    for (int kk = 0; kk < 64; kk += 16) {
        uint32_t bhf[4][2], blf[4][2];
        const int krow = kk + ((lane >> 3) & 1) * 8 + (lane & 7);
        const int cadd = (lane >> 4) * 8;
#pragma unroll
        for (int np = 0; np < 2; np++) {
            const int bcol = wn * 32 + np * 16 + cadd;
            const uint32_t off = (uint32_t)(krow * FSB + bcol) * 2;
            ldsm_x4_t(bhf[2 * np][0], bhf[2 * np][1], bhf[2 * np + 1][0], bhf[2 * np + 1][1],
                      bh_u + off);
            ldsm_x4_t(blf[2 * np][0], blf[2 * np][1], blf[2 * np + 1][0], blf[2 * np + 1][1],
                      bl_u + off);
        }
#pragma unroll
        for (int mi = 0; mi < 4; mi++) {
            const int arow = wm * 64 + mi * 16 + (lane & 15);
            const int acol = kk + (lane >> 4) * 8;
            const uint32_t off = (arow * FSA + acol) * 2;
            uint32_t ahf[4], alf[4];
            ldsm_x4(ahf[0], ahf[1], ahf[2], ahf[3], ah_u + off);
            ldsm_x4(alf[0], alf[1], alf[2], alf[3], al_u + off);
#pragma unroll
            for (int ni = 0; ni < 4; ni++) {
                mma_bf16(acc[mi][ni], ahf, bhf[ni]);
                mma_bf16(acc[mi][ni], ahf, blf[ni]);
                mma_bf16(acc[mi][ni], alf, bhf[ni]);
            }
        }
    }

    const int qr = lane >> 2, qc = (lane & 3) * 2;
#pragma unroll
    for (int mi = 0; mi < 4; mi++) {
        const int n = n0 + wm * 64 + mi * 16 + qr;
#pragma unroll
        for (int ni = 0; ni < 4; ni++) {
            const int h = h0 + wn * 32 + ni * 8 + qc;
            const float b0 = o_b[h], b1 = o_b[h + 1];
            *reinterpret_cast<float2*>(&out[(size_t)n * HID + h]) =
                make_float2(acc[mi][ni][0] + b0, acc[mi][ni][1] + b1);
            *reinterpret_cast<float2*>(&out[(size_t)(n + 8) * HID + h]) =
                make_float2(acc[mi][ni][2] + b0, acc[mi][ni][3] + b1);
        }
    }
}

// ---------------- launch ----------------
extern "C" void kernel_launch(void* const* d_in, const int* in_sizes, int n_in,
                              void* d_out, int out_size) {
    const float* hs     = (const float*)d_in[0];
    const float* slots  = (const float*)d_in[2];
    const float* q_w    = (const float*)d_in[3];
    const float* q_b    = (const float*)d_in[4];
    const float* v_w    = (const float*)d_in[7];
    const float* v_b    = (const float*)d_in[8];
    const float* gate_w = (const float*)d_in[9];
    const float* gate_b = (const float*)d_in[10];
    const float* o_w    = (const float*)d_in[11];
    const float* o_b    = (const float*)d_in[12];

    float* out       = (float*)d_out;
    float* gates_out = out + (size_t)BNTOK * HID;

    cudaFuncSetAttribute(k_logits_f, cudaFuncAttributeMaxDynamicSharedMemorySize, LG_SMEM);
    cudaFuncSetAttribute(k_X_h, cudaFuncAttributeMaxDynamicSharedMemorySize, XSM_BYTES);
    cudaFuncSetAttribute(k_final_h, cudaFuncAttributeMaxDynamicSharedMemorySize, FSM_BYTES);

    k_qsw      <<<dim3(HID / 128, 4), 128>>>(slots, q_w, q_b);
    k_wg       <<<256, 256>>>(gate_w);
    k_logits_f <<<BNTOK / 128, 512, LG_SMEM>>>(hs, gate_b, gates_out);
    k_X_h      <<<dim3(HID / 128, BATCH, NXC), 256, XSM_BYTES>>>(hs);
    k_sv       <<<dim3(2, BATCH, KSP), 256>>>(v_w);
    k_so       <<<dim3(HID / 128, BATCH), 256>>>(o_w, v_b);
    k_final_h  <<<dim3(BNTOK / 128, HID / 128), 256, FSM_BYTES>>>(gates_out, o_b, out);
}